// round 5
// baseline (speedup 1.0000x reference)
#include <cuda_runtime.h>

#define WIN    100
#define H      64
#define AA     64
#define KK     8
#define NAPP   4
#define DT     0.1f
#define LN_EPS 1e-5f
#define TPB    128

// Transposed-weight row stride: 68 floats (pad 64 -> 4-way instead of 32-way
// STS conflicts on the transpose scatter; 68*4B = 272B, 16B-aligned rows).
#define TSTRIDE     68
#define SW_FLOATS   (TSTRIDE * (WIN + AA))      // 11152: We_t rows then Wr_t rows
#define SY_STRIDE   (WIN + 1)                   // pad -> conflict-free LDS
#define SY_FLOATS   (TPB * SY_STRIDE)           // 12928
#define DYN_BYTES   ((SW_FLOATS + SY_FLOATS) * sizeof(float))   // 96,320 B

__device__ __forceinline__ float softplus_f(float v) {
    return (v > 20.f) ? v : log1pf(expf(v));
}

// d += a * b on packed f32x2 (SASS FFMA2; only reachable via PTX).
// No volatile: pure value computation, let ptxas schedule freely.
__device__ __forceinline__ void ffma2(float2& d, float ax, float ay, float bx, float by) {
    asm("{\n\t"
        ".reg .b64 ra, rb, rd;\n\t"
        "mov.b64 ra, {%2, %3};\n\t"
        "mov.b64 rb, {%4, %5};\n\t"
        "mov.b64 rd, {%0, %1};\n\t"
        "fma.rn.f32x2 rd, ra, rb, rd;\n\t"
        "mov.b64 {%0, %1}, rd;\n\t"
        "}"
        : "+f"(d.x), "+f"(d.y)
        : "f"(ax), "f"(ay), "f"(bx), "f"(by));
}

__global__ __launch_bounds__(TPB, 2)
void pinn_lnn_ista_kernel(
    const float* __restrict__ y,         // (B, WIN)
    const float* __restrict__ w_in,      // (H)
    const float* __restrict__ b_in,      // (H)
    const float* __restrict__ tau_param, // (H)
    const float* __restrict__ W_rec,     // (H, H)
    const float* __restrict__ ln_w,      // (H)
    const float* __restrict__ ln_b,      // (H)
    const float* __restrict__ Wx0,       // (A, H)
    const float* __restrict__ bx0,       // (A)
    const float* __restrict__ We,        // (K, A, WIN)
    const float* __restrict__ be,        // (K, A)
    const float* __restrict__ Wr,        // (K, A, A)
    const float* __restrict__ thr,       // (K, A)
    const float* __restrict__ head_W,    // (NAPP, A)
    const float* __restrict__ head_b,    // (NAPP)
    float* __restrict__ out_power,       // (B, NAPP)
    float* __restrict__ out_x,           // (B, A)
    int B)
{
    extern __shared__ __align__(16) float smem[];
    float* sW = smem;                    // phase1: W_rec/Wx0 linear; phase3: We_t/Wr_t padded
    float* sy = smem + SW_FLOATS;        // (TPB, WIN+1) staged y tile

    __shared__ float s_win[H], s_bin[H], s_lnw[H], s_lnb[H], s_decay[H];
    __shared__ float s_vec[AA];          // bx0 / be_k
    __shared__ float s_lam[AA];          // softplus(thr_k)

    const int tid = threadIdx.x;
    const int b0  = blockIdx.x * TPB;
    const int b   = b0 + tid;
    const bool active = (b < B);

    // ---- stage y tile (coalesced gmem -> padded smem) ----
    {
        const float* ybase = y + (long)b0 * WIN;
        for (int idx = tid; idx < TPB * WIN; idx += TPB) {
            const int r = idx / WIN;
            const int t = idx - r * WIN;
            if (b0 + r < B) sy[r * SY_STRIDE + t] = ybase[idx];
        }
    }
    // ---- stage phase-1 weights (linear layout in sW) ----
    for (int i = tid; i < H * H; i += TPB) sW[i] = W_rec[i];
    if (tid < H) {
        s_win[tid]   = w_in[tid];
        s_bin[tid]   = b_in[tid];
        s_lnw[tid]   = ln_w[tid];
        s_lnb[tid]   = ln_b[tid];
        s_decay[tid] = DT / softplus_f(tau_param[tid]);
    }
    __syncthreads();

    const float* yrow_s = sy + tid * SY_STRIDE;

    // ================= Phase 1: LNN recurrence =================
    float h[H];
    #pragma unroll
    for (int j = 0; j < H; j++) h[j] = 0.f;

    if (active) {
        const float4* sW4 = reinterpret_cast<const float4*>(sW);
        for (int t = 0; t < WIN; t++) {
            const float xt = yrow_s[t];
            float2 pre2[H / 2];
            #pragma unroll
            for (int j2 = 0; j2 < H / 2; j2++) {
                pre2[j2].x = fmaf(xt, s_win[2 * j2],     s_bin[2 * j2]);
                pre2[j2].y = fmaf(xt, s_win[2 * j2 + 1], s_bin[2 * j2 + 1]);
            }
            #pragma unroll 4
            for (int i = 0; i < H; i++) {
                const float hv = h[i];
                #pragma unroll
                for (int j4 = 0; j4 < H / 4; j4++) {
                    const float4 w = sW4[i * (H / 4) + j4];
                    ffma2(pre2[2 * j4],     hv, hv, w.x, w.y);
                    ffma2(pre2[2 * j4 + 1], hv, hv, w.z, w.w);
                }
            }
            // layernorm over H
            float mean = 0.f;
            #pragma unroll
            for (int j2 = 0; j2 < H / 2; j2++) mean += pre2[j2].x + pre2[j2].y;
            mean *= (1.f / H);
            float var = 0.f;
            #pragma unroll
            for (int j2 = 0; j2 < H / 2; j2++) {
                const float dx = pre2[j2].x - mean;
                const float dy = pre2[j2].y - mean;
                var = fmaf(dx, dx, var);
                var = fmaf(dy, dy, var);
            }
            var *= (1.f / H);
            const float rstd = rsqrtf(var + LN_EPS);
            #pragma unroll
            for (int j2 = 0; j2 < H / 2; j2++) {
                #pragma unroll
                for (int c = 0; c < 2; c++) {
                    const int j = 2 * j2 + c;
                    const float p = (c == 0) ? pre2[j2].x : pre2[j2].y;
                    const float f = tanhf(fmaf((p - mean) * rstd, s_lnw[j], s_lnb[j]));
                    float hn = fmaf(-h[j], s_decay[j], h[j]) + DT * f;
                    hn = fminf(10.f, fmaxf(-10.f, hn));
                    h[j] = hn;
                }
            }
        }
    }

    // ================= Phase 2: warm start x = h @ Wx0^T + bx0 =================
    __syncthreads();
    for (int i = tid; i < AA * H; i += TPB) sW[i] = Wx0[i];
    if (tid < AA) s_vec[tid] = bx0[tid];
    __syncthreads();

    float x[AA];
    if (active) {
        #pragma unroll 4
        for (int a = 0; a < AA; a++) {
            float acc = s_vec[a];
            #pragma unroll
            for (int i = 0; i < H; i++)
                acc = fmaf(h[i], sW[a * H + i], acc);
            x[a] = acc;
        }
    }

    // ================= Phase 3: ISTA iterations =================
    float* sWe_t = sW;                       // (WIN, TSTRIDE)  row t -> We[:,t]
    float* sWr_t = sW + WIN * TSTRIDE;       // (AA,  TSTRIDE)  row i -> Wr[:,i]

    for (int k = 0; k < KK; k++) {
        __syncthreads();
        {
            // Coalesced gmem reads (linear idx), scatter into padded transposed
            // smem rows (4-way STS conflict max, issue-only cost).
            const float* Wek = We + (long)k * AA * WIN;
            const float* Wrk = Wr + (long)k * AA * AA;
            for (int idx = tid; idx < AA * WIN; idx += TPB) {
                const int a = idx / WIN;
                const int t = idx - a * WIN;
                sWe_t[t * TSTRIDE + a] = Wek[idx];
            }
            for (int idx = tid; idx < AA * AA; idx += TPB) {
                const int a = idx / AA;
                const int i = idx - a * AA;
                sWr_t[i * TSTRIDE + a] = Wrk[idx];
            }
            if (tid < AA) {
                s_vec[tid] = be[k * AA + tid];
                s_lam[tid] = softplus_f(thr[k * AA + tid]);
            }
        }
        __syncthreads();

        if (active) {
            const float4* sWe4 = reinterpret_cast<const float4*>(sWe_t);
            const float4* sWr4 = reinterpret_cast<const float4*>(sWr_t);

            float2 z2[AA / 2];
            #pragma unroll
            for (int a2 = 0; a2 < AA / 2; a2++) {
                z2[a2].x = s_vec[2 * a2];
                z2[a2].y = s_vec[2 * a2 + 1];
            }
            // z += y @ We_k^T   (We staged t-major, padded rows)
            #pragma unroll 4
            for (int t = 0; t < WIN; t++) {
                const float yt = yrow_s[t];
                #pragma unroll
                for (int a4 = 0; a4 < AA / 4; a4++) {
                    const float4 w = sWe4[t * (TSTRIDE / 4) + a4];
                    ffma2(z2[2 * a4],     yt, yt, w.x, w.y);
                    ffma2(z2[2 * a4 + 1], yt, yt, w.z, w.w);
                }
            }
            // z += x @ Wr_k^T   (Wr staged i-major, padded rows)
            #pragma unroll 4
            for (int i = 0; i < AA; i++) {
                const float xv = x[i];
                #pragma unroll
                for (int a4 = 0; a4 < AA / 4; a4++) {
                    const float4 w = sWr4[i * (TSTRIDE / 4) + a4];
                    ffma2(z2[2 * a4],     xv, xv, w.x, w.y);
                    ffma2(z2[2 * a4 + 1], xv, xv, w.z, w.w);
                }
            }
            // soft threshold
            #pragma unroll
            for (int a2 = 0; a2 < AA / 2; a2++) {
                const float zx = z2[a2].x, zy = z2[a2].y;
                float mx = fmaxf(fabsf(zx) - s_lam[2 * a2],     0.f);
                float my = fmaxf(fabsf(zy) - s_lam[2 * a2 + 1], 0.f);
                x[2 * a2]     = copysignf(mx, zx);
                x[2 * a2 + 1] = copysignf(my, zy);
            }
        }
    }

    // ================= Phase 4: heads + outputs =================
    if (active) {
        #pragma unroll
        for (int n = 0; n < NAPP; n++) {
            float acc = __ldg(&head_b[n]);
            #pragma unroll
            for (int a = 0; a < AA; a++)
                acc = fmaf(x[a], __ldg(&head_W[n * AA + a]), acc);
            out_power[(long)b * NAPP + n] = acc;
        }
        #pragma unroll
        for (int a = 0; a < AA; a++)
            out_x[(long)b * AA + a] = x[a];
    }
}

extern "C" void kernel_launch(void* const* d_in, const int* in_sizes, int n_in,
                              void* d_out, int out_size)
{
    const float* y         = (const float*)d_in[0];
    const float* w_in      = (const float*)d_in[1];
    const float* b_in      = (const float*)d_in[2];
    const float* tau_param = (const float*)d_in[3];
    const float* W_rec     = (const float*)d_in[4];
    const float* ln_w      = (const float*)d_in[5];
    const float* ln_b      = (const float*)d_in[6];
    const float* Wx0       = (const float*)d_in[7];
    const float* bx0       = (const float*)d_in[8];
    const float* We        = (const float*)d_in[9];
    const float* be        = (const float*)d_in[10];
    const float* Wr        = (const float*)d_in[11];
    const float* thr       = (const float*)d_in[12];
    const float* head_W    = (const float*)d_in[13];
    const float* head_b    = (const float*)d_in[14];

    const int B = in_sizes[0] / WIN;

    float* out       = (float*)d_out;
    float* out_power = out;                      // (B, NAPP) first
    float* out_x     = out + (size_t)B * NAPP;   // (B, A) second

    cudaFuncSetAttribute(pinn_lnn_ista_kernel,
                         cudaFuncAttributeMaxDynamicSharedMemorySize,
                         (int)DYN_BYTES);

    const int grid = (B + TPB - 1) / TPB;
    pinn_lnn_ista_kernel<<<grid, TPB, DYN_BYTES>>>(
        y, w_in, b_in, tau_param, W_rec, ln_w, ln_b,
        Wx0, bx0, We, be, Wr, thr, head_W, head_b,
        out_power, out_x, B);
}